// round 2
// baseline (speedup 1.0000x reference)
#include <cuda_runtime.h>
#include <cuda_fp16.h>
#include <cuda_bf16.h>
#include <cstdint>

#define M_TOTAL 4096
#define N_TOTAL 4096
#define K_TOTAL 4096
#define GROUP_SIZE 128
#define NGROUPS (K_TOTAL / GROUP_SIZE)   // 32

// Scratch (device globals: allocation-free rule)
__device__ __half g_Wd[(size_t)N_TOTAL * K_TOTAL];   // dequantized weights fp16
__device__ __half g_X[(size_t)M_TOTAL * K_TOTAL];    // activations converted to fp16
__device__ int    g_dtype;                           // 0=f16, 1=f32, 2=bf16

// ---------------------------------------------------------------------------
// Dtype detection: interpret x as f16/f32/bf16, count plausible N(0,1) values.
// ---------------------------------------------------------------------------
__device__ __forceinline__ int plausible(float v) {
    return (v == v) && (fabsf(v) < 16.0f) && (fabsf(v) > 5e-4f);
}

__global__ void detect_dtype_kernel(const void* __restrict__ x) {
    __shared__ int s[3];
    if (threadIdx.x < 3) s[threadIdx.x] = 0;
    __syncthreads();
    int c0 = 0, c1 = 0, c2 = 0;
    for (int i = threadIdx.x; i < 4096; i += blockDim.x) {
        float v0 = __half2float(((const __half*)x)[i]);
        float v1 = ((const float*)x)[i];
        float v2 = __bfloat162float(((const __nv_bfloat16*)x)[i]);
        c0 += plausible(v0);
        c1 += plausible(v1);
        c2 += plausible(v2);
    }
    atomicAdd(&s[0], c0);
    atomicAdd(&s[1], c1);
    atomicAdd(&s[2], c2);
    __syncthreads();
    if (threadIdx.x == 0) {
        int best = 0;
        if (s[1] > s[best]) best = 1;
        if (s[2] > s[best]) best = 2;
        g_dtype = best;
    }
}

__device__ __forceinline__ float load_elem(const void* p, size_t idx, int flag) {
    if (flag == 1) return ((const float*)p)[idx];
    if (flag == 2) return __bfloat162float(((const __nv_bfloat16*)p)[idx]);
    return __half2float(((const __half*)p)[idx]);
}

// ---------------------------------------------------------------------------
// Convert x -> fp16 scratch (8 elements / thread)
// ---------------------------------------------------------------------------
__global__ void convert_x_kernel(const void* __restrict__ x) {
    const int flag = g_dtype;
    size_t base = ((size_t)blockIdx.x * blockDim.x + threadIdx.x) * 8;
    if (base >= (size_t)M_TOTAL * K_TOTAL) return;
    __half out[8];
    if (flag == 0) {
        *reinterpret_cast<uint4*>(out) = *reinterpret_cast<const uint4*>((const __half*)x + base);
    } else if (flag == 1) {
        const float4* fp = reinterpret_cast<const float4*>((const float*)x + base);
        float4 f0 = fp[0], f1 = fp[1];
        out[0] = __float2half(f0.x); out[1] = __float2half(f0.y);
        out[2] = __float2half(f0.z); out[3] = __float2half(f0.w);
        out[4] = __float2half(f1.x); out[5] = __float2half(f1.y);
        out[6] = __float2half(f1.z); out[7] = __float2half(f1.w);
    } else {
        const __nv_bfloat16* bp = (const __nv_bfloat16*)x + base;
        uint4 raw = *reinterpret_cast<const uint4*>(bp);
        const __nv_bfloat16* b = reinterpret_cast<const __nv_bfloat16*>(&raw);
#pragma unroll
        for (int i = 0; i < 8; i++) out[i] = __float2half(__bfloat162float(b[i]));
    }
    *reinterpret_cast<uint4*>(g_X + base) = *reinterpret_cast<uint4*>(out);
}

// ---------------------------------------------------------------------------
// Dequant: W = (half(W_q) - zero[g]) * scale[g], fp16 math (matches reference)
// ---------------------------------------------------------------------------
__global__ void dequant_kernel(const int* __restrict__ Wq,
                               const void* __restrict__ scale,
                               const void* __restrict__ zero) {
    const int flag = g_dtype;
    size_t base = ((size_t)blockIdx.x * blockDim.x + threadIdx.x) * 8;
    if (base >= (size_t)N_TOTAL * K_TOTAL) return;
    int n = (int)(base / K_TOTAL);
    int k = (int)(base % K_TOTAL);
    int g = k / GROUP_SIZE;
    __half s = __float2half(load_elem(scale, (size_t)n * NGROUPS + g, flag));
    __half z = __float2half(load_elem(zero,  (size_t)n * NGROUPS + g, flag));

    const int4* wp = reinterpret_cast<const int4*>(Wq + base);
    int4 w0 = wp[0];
    int4 w1 = wp[1];
    int wv[8] = {w0.x, w0.y, w0.z, w0.w, w1.x, w1.y, w1.z, w1.w};

    __half out[8];
#pragma unroll
    for (int i = 0; i < 8; i++) {
        out[i] = __hmul(__hsub(__int2half_rn(wv[i]), z), s);
    }
    *reinterpret_cast<uint4*>(g_Wd + base) = *reinterpret_cast<uint4*>(out);
}

// ---------------------------------------------------------------------------
// NT GEMM  C[M,N] = X[M,K] * Wd[N,K]^T + bias
// mma.sync.m16n8k16 fp16 -> fp32 accum, cp.async double-buffered smem.
// ---------------------------------------------------------------------------
#define BM 128
#define BN 128
#define BK 32
#define BKP 40

__device__ __forceinline__ void cp_async16(void* smem, const void* gmem) {
    uint32_t s = (uint32_t)__cvta_generic_to_shared(smem);
    asm volatile("cp.async.cg.shared.global [%0], [%1], 16;\n" :: "r"(s), "l"(gmem));
}
__device__ __forceinline__ void cp_commit() {
    asm volatile("cp.async.commit_group;\n");
}
template <int N>
__device__ __forceinline__ void cp_wait() {
    asm volatile("cp.async.wait_group %0;\n" :: "n"(N));
}

__global__ __launch_bounds__(256) void gemm_kernel(const void* __restrict__ bias,
                                                   void* __restrict__ C) {
    __shared__ __align__(16) __half As[2][BM][BKP];
    __shared__ __align__(16) __half Bs[2][BN][BKP];

    const int flag = g_dtype;
    const int tid = threadIdx.x;
    const int lane = tid & 31;
    const int warp = tid >> 5;
    const int warp_m = warp & 1;
    const int warp_n = warp >> 1;

    const int bm = blockIdx.y * BM;
    const int bn = blockIdx.x * BN;

    float acc[4][4][4];
#pragma unroll
    for (int mi = 0; mi < 4; mi++)
#pragma unroll
        for (int ni = 0; ni < 4; ni++)
#pragma unroll
            for (int r = 0; r < 4; r++) acc[mi][ni][r] = 0.0f;

    auto load_tile = [&](int buf, int k0) {
#pragma unroll
        for (int i = 0; i < 2; i++) {
            int chunk = tid + i * 256;
            int row = chunk >> 2;
            int col = (chunk & 3) * 8;
            cp_async16(&As[buf][row][col],
                       g_X + (size_t)(bm + row) * K_TOTAL + k0 + col);
            cp_async16(&Bs[buf][row][col],
                       g_Wd + (size_t)(bn + row) * K_TOTAL + k0 + col);
        }
    };

    const int NK = K_TOTAL / BK;
    load_tile(0, 0);
    cp_commit();

    for (int kt = 0; kt < NK; kt++) {
        int buf = kt & 1;
        if (kt + 1 < NK) {
            load_tile(buf ^ 1, (kt + 1) * BK);
            cp_commit();
            cp_wait<1>();
        } else {
            cp_wait<0>();
        }
        __syncthreads();

#pragma unroll
        for (int ks = 0; ks < 2; ks++) {
            uint32_t a[4][4];
#pragma unroll
            for (int mi = 0; mi < 4; mi++) {
                int row = warp_m * 64 + mi * 16 + (lane & 15);
                int col = ks * 16 + ((lane >> 4) << 3);
                uint32_t addr = (uint32_t)__cvta_generic_to_shared(&As[buf][row][col]);
                asm volatile(
                    "ldmatrix.sync.aligned.m8n8.x4.shared.b16 {%0,%1,%2,%3}, [%4];\n"
                    : "=r"(a[mi][0]), "=r"(a[mi][1]), "=r"(a[mi][2]), "=r"(a[mi][3])
                    : "r"(addr));
            }
            uint32_t b[4][2];
#pragma unroll
            for (int ni = 0; ni < 4; ni++) {
                int row = warp_n * 32 + ni * 8 + (lane & 7);
                int col = ks * 16 + ((lane >> 3) & 1) * 8;
                uint32_t addr = (uint32_t)__cvta_generic_to_shared(&Bs[buf][row][col]);
                asm volatile(
                    "ldmatrix.sync.aligned.m8n8.x2.shared.b16 {%0,%1}, [%2];\n"
                    : "=r"(b[ni][0]), "=r"(b[ni][1])
                    : "r"(addr));
            }
#pragma unroll
            for (int mi = 0; mi < 4; mi++) {
#pragma unroll
                for (int ni = 0; ni < 4; ni++) {
                    asm volatile(
                        "mma.sync.aligned.m16n8k16.row.col.f32.f16.f16.f32 "
                        "{%0,%1,%2,%3}, {%4,%5,%6,%7}, {%8,%9}, {%0,%1,%2,%3};\n"
                        : "+f"(acc[mi][ni][0]), "+f"(acc[mi][ni][1]),
                          "+f"(acc[mi][ni][2]), "+f"(acc[mi][ni][3])
                        : "r"(a[mi][0]), "r"(a[mi][1]), "r"(a[mi][2]), "r"(a[mi][3]),
                          "r"(b[ni][0]), "r"(b[ni][1]));
                }
            }
        }
        __syncthreads();
    }

    // Epilogue: bias + store in detected output dtype
#pragma unroll
    for (int mi = 0; mi < 4; mi++) {
#pragma unroll
        for (int ni = 0; ni < 4; ni++) {
            int m0 = bm + warp_m * 64 + mi * 16 + (lane >> 2);
            int n0 = bn + warp_n * 32 + ni * 8 + (lane & 3) * 2;
            float b0 = load_elem(bias, n0, flag);
            float b1 = load_elem(bias, n0 + 1, flag);
            float v00 = acc[mi][ni][0] + b0, v01 = acc[mi][ni][1] + b1;
            float v10 = acc[mi][ni][2] + b0, v11 = acc[mi][ni][3] + b1;
            size_t off0 = (size_t)m0 * N_TOTAL + n0;
            size_t off1 = (size_t)(m0 + 8) * N_TOTAL + n0;
            if (flag == 1) {
                *reinterpret_cast<float2*>((float*)C + off0) = make_float2(v00, v01);
                *reinterpret_cast<float2*>((float*)C + off1) = make_float2(v10, v11);
            } else if (flag == 2) {
                __nv_bfloat162 p0 = __floats2bfloat162_rn(v00, v01);
                __nv_bfloat162 p1 = __floats2bfloat162_rn(v10, v11);
                *reinterpret_cast<__nv_bfloat162*>((__nv_bfloat16*)C + off0) = p0;
                *reinterpret_cast<__nv_bfloat162*>((__nv_bfloat16*)C + off1) = p1;
            } else {
                *reinterpret_cast<__half2*>((__half*)C + off0) = __floats2half2_rn(v00, v01);
                *reinterpret_cast<__half2*>((__half*)C + off1) = __floats2half2_rn(v10, v11);
            }
        }
    }
}

// ---------------------------------------------------------------------------
// Launch. Resolve input order from in_sizes (handles dict vs sorted metadata):
//   dict order:  x(16.7M f), W_q(16.7M i), scale(131072), zero(131072), bias(4096)
//   alpha order: W_q(16.7M), bias(4096), scale(131072), x(16.7M), zero(131072)
// ---------------------------------------------------------------------------
extern "C" void kernel_launch(void* const* d_in, const int* in_sizes, int n_in,
                              void* d_out, int out_size) {
    int ix = 0, iw = 1, is = 2, iz = 3, ib = 4;  // dict order default
    if (n_in >= 5 && in_sizes[1] == 4096) {      // alphabetical order
        iw = 0; ib = 1; is = 2; ix = 3; iz = 4;
    }
    const void* x     = d_in[ix];
    const int*  Wq    = (const int*)d_in[iw];
    const void* scale = d_in[is];
    const void* zero  = d_in[iz];
    const void* bias  = d_in[ib];

    detect_dtype_kernel<<<1, 256>>>(x);

    {
        size_t total8 = (size_t)M_TOTAL * K_TOTAL / 8;
        convert_x_kernel<<<(int)((total8 + 255) / 256), 256>>>(x);
    }
    {
        size_t total8 = (size_t)N_TOTAL * K_TOTAL / 8;
        dequant_kernel<<<(int)((total8 + 255) / 256), 256>>>(Wq, scale, zero);
    }
    {
        dim3 grid(N_TOTAL / BN, M_TOTAL / BM);
        gemm_kernel<<<grid, 256>>>(bias, d_out);
    }
}

// round 5
// speedup vs baseline: 2.7714x; 2.7714x over previous
#include <cuda_runtime.h>
#include <cuda.h>
#include <cuda_fp16.h>
#include <cuda_bf16.h>
#include <cstdint>

#define M_TOTAL 4096
#define N_TOTAL 4096
#define K_TOTAL 4096
#define GROUP_SIZE 128
#define NGROUPS (K_TOTAL / GROUP_SIZE)   // 32

// Arch-specific feature gate: tcgen05/TMEM exist only in the sm_103a/sm_100a
// device passes. The plain compute_103 pass compiles a stub (never executed:
// runtime selects the exact-arch sm_103a SASS).
#if defined(__CUDA_ARCH_FEAT_SM103_ALL) || defined(__CUDA_ARCH_FEAT_SM100_ALL) || \
    (defined(__CUDA_ARCH_SPECIFIC__) && (__CUDA_ARCH_SPECIFIC__ >= 1000))
#define HAS_TCGEN05 1
#else
#define HAS_TCGEN05 0
#endif

// Scratch (device globals: allocation-free rule)
__device__ __half g_Wd[(size_t)N_TOTAL * K_TOTAL];   // dequantized weights fp16 [N,K]
__device__ __half g_X[(size_t)M_TOTAL * K_TOTAL];    // activations fp16 [M,K]
__device__ int    g_dtype;                           // 0=f16, 1=f32, 2=bf16

// ===========================================================================
// PTX helpers
// ===========================================================================
__device__ __forceinline__ uint32_t elect_one_pred() {
    uint32_t pred;
    asm volatile(
        "{\n\t.reg .pred p;\n\telect.sync _|p, 0xFFFFFFFF;\n\t"
        "selp.b32 %0, 1, 0, p;\n\t}"
        : "=r"(pred));
    return pred;
}
__device__ __forceinline__ uint32_t smem_to_u32(const void* p) {
    uint32_t a;
    asm("{ .reg .u64 t; cvta.to.shared.u64 t, %1; cvt.u32.u64 %0, t; }" : "=r"(a) : "l"(p));
    return a;
}

#define MBARRIER_INIT(addr, cnt) \
    asm volatile("mbarrier.init.shared.b64 [%0], %1;" :: "r"((uint32_t)(addr)), "r"((uint32_t)(cnt)) : "memory")
#define MBARRIER_EXPECT_TX(addr, bytes) \
    asm volatile("mbarrier.arrive.expect_tx.shared.b64 _, [%0], %1;" :: "r"((uint32_t)(addr)), "r"((uint32_t)(bytes)) : "memory")

#define MBARRIER_WAIT_PARITY(mbar_addr, phase_parity) do { \
    uint32_t _mbar = (uint32_t)(mbar_addr); \
    uint32_t _par = (uint32_t)(phase_parity); \
    uint32_t _done; \
    asm volatile("{\n\t.reg .pred p;\n\t" \
        "mbarrier.try_wait.parity.acquire.cta.shared::cta.b64 p, [%1], %2;\n\t" \
        "selp.b32 %0, 1, 0, p;\n\t}" : "=r"(_done) : "r"(_mbar), "r"(_par) : "memory"); \
    if (!_done) { \
        asm volatile("{\n\t.reg .pred P1;\n\t" \
            "WAIT_LOOP_%=:\n\t" \
            "mbarrier.try_wait.parity.acquire.cta.shared::cta.b64 P1, [%0], %1, 0x989680;\n\t" \
            "@P1 bra.uni WAIT_DONE_%=;\n\t" \
            "bra.uni WAIT_LOOP_%=;\n\t" \
            "WAIT_DONE_%=:\n\t}" :: "r"(_mbar), "r"(_par) : "memory"); \
    } \
} while(0)

#if HAS_TCGEN05
#define TCGEN05_ALLOC(smem_addr, nCols) \
    asm volatile("tcgen05.alloc.cta_group::1.sync.aligned.shared::cta.b32 [%0], %1;" \
        :: "r"((uint32_t)(smem_addr)), "r"((uint32_t)(nCols)) : "memory")
#define TCGEN05_DEALLOC(tmem_addr, nCols) \
    asm volatile("tcgen05.dealloc.cta_group::1.sync.aligned.b32 %0, %1;" :: "r"(tmem_addr), "r"((uint32_t)(nCols)))
#define TCGEN05_RELINQUISH() \
    asm volatile("tcgen05.relinquish_alloc_permit.cta_group::1.sync.aligned;")
#define TCGEN05_COMMIT(mbar) \
    asm volatile("tcgen05.commit.cta_group::1.mbarrier::arrive::one.shared::cluster.b64 [%0];" \
        :: "r"((uint32_t)(mbar)) : "memory")
#define TCGEN05_FENCE_AFTER() \
    asm volatile("tcgen05.fence::after_thread_sync;" ::: "memory")
#define TCGEN05_FENCE_BEFORE() \
    asm volatile("tcgen05.fence::before_thread_sync;" ::: "memory")
#define TCGEN05_WAIT_LD() \
    asm volatile("tcgen05.wait::ld.sync.aligned;" ::: "memory")

#define TCGEN05_LD_32X32B_X32(r, tmem_addr) \
    asm volatile( \
        "tcgen05.ld.sync.aligned.32x32b.x32.b32 " \
        "{%0, %1, %2, %3, %4, %5, %6, %7, " \
        " %8, %9, %10, %11, %12, %13, %14, %15, " \
        " %16, %17, %18, %19, %20, %21, %22, %23, " \
        " %24, %25, %26, %27, %28, %29, %30, %31}, [%32];" \
        : "=r"((r)[0]),  "=r"((r)[1]),  "=r"((r)[2]),  "=r"((r)[3]), \
          "=r"((r)[4]),  "=r"((r)[5]),  "=r"((r)[6]),  "=r"((r)[7]), \
          "=r"((r)[8]),  "=r"((r)[9]),  "=r"((r)[10]), "=r"((r)[11]), \
          "=r"((r)[12]), "=r"((r)[13]), "=r"((r)[14]), "=r"((r)[15]), \
          "=r"((r)[16]), "=r"((r)[17]), "=r"((r)[18]), "=r"((r)[19]), \
          "=r"((r)[20]), "=r"((r)[21]), "=r"((r)[22]), "=r"((r)[23]), \
          "=r"((r)[24]), "=r"((r)[25]), "=r"((r)[26]), "=r"((r)[27]), \
          "=r"((r)[28]), "=r"((r)[29]), "=r"((r)[30]), "=r"((r)[31]) \
        : "r"(tmem_addr))
#endif  // HAS_TCGEN05

#define TMA_LOAD_2D(smem_addr, map, cx, cy, mbar) \
    asm volatile( \
        "cp.async.bulk.tensor.2d.shared::cta.global.tile.mbarrier::complete_tx::bytes " \
        "[%0], [%1, {%2, %3}], [%4];" \
        :: "r"((uint32_t)(smem_addr)), "l"(map), "r"((int)(cx)), "r"((int)(cy)), \
           "r"((uint32_t)(mbar)) : "memory")

// SW128 K-major smem descriptor (LBO=1, SBO=64, version=1, layout=2)
static constexpr uint64_t SMEM_DESC_BASE_SW128 =
    (uint64_t(2) << 61) | (uint64_t(1) << 46) | (uint64_t(64) << 32) | (uint64_t(1) << 16);
#define MAKE_SMEM_DESC(base_addr) \
    (SMEM_DESC_BASE_SW128 | ((uint64_t)((base_addr) >> 4) & 0x3FFF))

#if HAS_TCGEN05
// SS f16 MMA, cg1: D[tmem] += A(desc) x B(desc)^T
__device__ __forceinline__ void mma_f16_ss(uint32_t d, uint64_t a, uint64_t b,
                                           uint32_t idesc, bool acc) {
    uint32_t en = acc ? 1u : 0u;
    asm volatile(
        "{\n\t.reg .pred p;\n\tsetp.ne.u32 p, %5, 0;\n\t"
        "tcgen05.mma.cta_group::1.kind::f16 [%0], %1, %2, %3, {%4, %4, %4, %4}, p;\n\t}"
        :: "r"(d), "l"(a), "l"(b), "r"(idesc), "r"(0u), "r"(en) : "memory");
}
#endif

// ===========================================================================
// dtype detection + conversion + dequant (arch-generic, unchanged)
// ===========================================================================
__device__ __forceinline__ int plausible(float v) {
    return (v == v) && (fabsf(v) < 16.0f) && (fabsf(v) > 5e-4f);
}

__global__ void detect_dtype_kernel(const void* __restrict__ x) {
    __shared__ int s[3];
    if (threadIdx.x < 3) s[threadIdx.x] = 0;
    __syncthreads();
    int c0 = 0, c1 = 0, c2 = 0;
    for (int i = threadIdx.x; i < 4096; i += blockDim.x) {
        c0 += plausible(__half2float(((const __half*)x)[i]));
        c1 += plausible(((const float*)x)[i]);
        c2 += plausible(__bfloat162float(((const __nv_bfloat16*)x)[i]));
    }
    atomicAdd(&s[0], c0); atomicAdd(&s[1], c1); atomicAdd(&s[2], c2);
    __syncthreads();
    if (threadIdx.x == 0) {
        int best = 0;
        if (s[1] > s[best]) best = 1;
        if (s[2] > s[best]) best = 2;
        g_dtype = best;
    }
}

__device__ __forceinline__ float load_elem(const void* p, size_t idx, int flag) {
    if (flag == 1) return ((const float*)p)[idx];
    if (flag == 2) return __bfloat162float(((const __nv_bfloat16*)p)[idx]);
    return __half2float(((const __half*)p)[idx]);
}

__global__ void convert_x_kernel(const void* __restrict__ x) {
    const int flag = g_dtype;
    size_t base = ((size_t)blockIdx.x * blockDim.x + threadIdx.x) * 8;
    if (base >= (size_t)M_TOTAL * K_TOTAL) return;
    __half out[8];
    if (flag == 0) {
        *reinterpret_cast<uint4*>(out) = *reinterpret_cast<const uint4*>((const __half*)x + base);
    } else if (flag == 1) {
        const float4* fp = reinterpret_cast<const float4*>((const float*)x + base);
        float4 f0 = fp[0], f1 = fp[1];
        out[0] = __float2half(f0.x); out[1] = __float2half(f0.y);
        out[2] = __float2half(f0.z); out[3] = __float2half(f0.w);
        out[4] = __float2half(f1.x); out[5] = __float2half(f1.y);
        out[6] = __float2half(f1.z); out[7] = __float2half(f1.w);
    } else {
        uint4 raw = *reinterpret_cast<const uint4*>((const __nv_bfloat16*)x + base);
        const __nv_bfloat16* b = reinterpret_cast<const __nv_bfloat16*>(&raw);
#pragma unroll
        for (int i = 0; i < 8; i++) out[i] = __float2half(__bfloat162float(b[i]));
    }
    *reinterpret_cast<uint4*>(g_X + base) = *reinterpret_cast<uint4*>(out);
}

__global__ void dequant_kernel(const int* __restrict__ Wq,
                               const void* __restrict__ scale,
                               const void* __restrict__ zero) {
    const int flag = g_dtype;
    size_t base = ((size_t)blockIdx.x * blockDim.x + threadIdx.x) * 8;
    if (base >= (size_t)N_TOTAL * K_TOTAL) return;
    int n = (int)(base / K_TOTAL);
    int k = (int)(base % K_TOTAL);
    int g = k / GROUP_SIZE;
    __half s = __float2half(load_elem(scale, (size_t)n * NGROUPS + g, flag));
    __half z = __float2half(load_elem(zero,  (size_t)n * NGROUPS + g, flag));

    const int4* wp = reinterpret_cast<const int4*>(Wq + base);
    int4 w0 = wp[0];
    int4 w1 = wp[1];
    int wv[8] = {w0.x, w0.y, w0.z, w0.w, w1.x, w1.y, w1.z, w1.w};

    __half out[8];
#pragma unroll
    for (int i = 0; i < 8; i++)
        out[i] = __hmul(__hsub(__int2half_rn(wv[i]), z), s);
    *reinterpret_cast<uint4*>(g_Wd + base) = *reinterpret_cast<uint4*>(out);
}

// ===========================================================================
// tcgen05 GEMM: C[M,N] = X[M,K] * Wd[N,K]^T + bias
// CTA tile 256x256, K-stage 64, 3-stage TMA pipeline, TMEM accumulators.
// ===========================================================================
#define BM 256
#define BN 256
#define BKT 64
#define NSTAGE 3
#define HALF_TILE_BYTES 16384         // 128 rows x 128B
#define STAGE_BYTES 65536             // A(32KB) + B(32KB)

__global__ __launch_bounds__(128, 1) void gemm_tc(
    const __grid_constant__ CUtensorMap tmA,
    const __grid_constant__ CUtensorMap tmB,
    const void* __restrict__ bias,
    void* __restrict__ C)
{
#if HAS_TCGEN05
    extern __shared__ __align__(1024) char smem[];
    const uint32_t sbase = smem_to_u32(smem);
    const uint32_t tbase = (sbase + 1024u) & ~1023u;   // tile region, 1024-aligned
    const int tid = threadIdx.x, wid = tid >> 5, lane = tid & 31;
    const int bm = blockIdx.y * BM, bn = blockIdx.x * BN;
    const int flag = g_dtype;

    const uint32_t full_mb = sbase + 8;    // 3 x 8B
    const uint32_t mma_mb  = sbase + 40;   // 3 x 8B

    if (tid == 0) {
        for (int s = 0; s < NSTAGE; s++) {
            MBARRIER_INIT(full_mb + s * 8, 1);
            MBARRIER_INIT(mma_mb  + s * 8, 1);
        }
    }
    if (wid == 0) {
        TCGEN05_ALLOC(sbase, 512);
        TCGEN05_RELINQUISH();
    }
    __syncthreads();
    uint32_t tmem;
    asm volatile("ld.shared.b32 %0, [%1];" : "=r"(tmem) : "r"(sbase));

    const int NKT = K_TOTAL / BKT;  // 64

    if (wid == 0) {
        // prologue: fill all stages
        if (elect_one_pred()) {
#pragma unroll
            for (int s = 0; s < NSTAGE; s++) {
                MBARRIER_EXPECT_TX(full_mb + s * 8, STAGE_BYTES);
                TMA_LOAD_2D(tbase + s * STAGE_BYTES,          &tmA, s * BKT, bm, full_mb + s * 8);
                TMA_LOAD_2D(tbase + s * STAGE_BYTES + 32768,  &tmB, s * BKT, bn, full_mb + s * 8);
            }
        }
        // idesc: F32 accum (bit4), F16 A/B (bits7-9,10-12 = 0), N=128 (bits17-22),
        // M=128 (bits24-28)
        const uint32_t idesc = (1u << 4) | (16u << 17) | (8u << 24);

        for (int kt = 0; kt < NKT; kt++) {
            const int s = kt % NSTAGE;
            const int r = kt / NSTAGE;
            MBARRIER_WAIT_PARITY(full_mb + s * 8, r & 1);
            if (elect_one_pred()) {
                const uint32_t aL = tbase + s * STAGE_BYTES;
                const uint32_t bL = aL + 32768;
                const uint64_t a0 = MAKE_SMEM_DESC(aL);
                const uint64_t a1 = MAKE_SMEM_DESC(aL + HALF_TILE_BYTES);
                const uint64_t b0 = MAKE_SMEM_DESC(bL);
                const uint64_t b1 = MAKE_SMEM_DESC(bL + HALF_TILE_BYTES);
#pragma unroll
                for (int ks = 0; ks < 4; ks++) {
                    const bool acc = !(kt == 0 && ks == 0);
                    mma_f16_ss(tmem + 0,   a0 + ks * 2, b0 + ks * 2, idesc, acc);
                    mma_f16_ss(tmem + 128, a0 + ks * 2, b1 + ks * 2, idesc, acc);
                    mma_f16_ss(tmem + 256, a1 + ks * 2, b0 + ks * 2, idesc, acc);
                    mma_f16_ss(tmem + 384, a1 + ks * 2, b1 + ks * 2, idesc, acc);
                }
                TCGEN05_COMMIT(mma_mb + s * 8);
            }
            if (kt + NSTAGE < NKT) {
                MBARRIER_WAIT_PARITY(mma_mb + s * 8, r & 1);  // buffer reusable
                if (elect_one_pred()) {
                    const int k0 = (kt + NSTAGE) * BKT;
                    MBARRIER_EXPECT_TX(full_mb + s * 8, STAGE_BYTES);
                    TMA_LOAD_2D(tbase + s * STAGE_BYTES,         &tmA, k0, bm, full_mb + s * 8);
                    TMA_LOAD_2D(tbase + s * STAGE_BYTES + 32768, &tmB, k0, bn, full_mb + s * 8);
                }
            }
        }
        {   // final MMA completion
            const int s = (NKT - 1) % NSTAGE, r = (NKT - 1) / NSTAGE;
            MBARRIER_WAIT_PARITY(mma_mb + s * 8, r & 1);
        }
    }
    __syncthreads();
    TCGEN05_FENCE_AFTER();

    // Epilogue: 4 warps read TMEM quadrants, add bias, store
#pragma unroll
    for (int q = 0; q < 4; q++) {
        const int m  = bm + (q >> 1) * 128 + wid * 32 + lane;
        const int nb = bn + (q & 1) * 128;
#pragma unroll
        for (int j = 0; j < 4; j++) {
            uint32_t r[32];
            TCGEN05_LD_32X32B_X32(r, tmem + q * 128 + j * 32);
            TCGEN05_WAIT_LD();
            const int n0 = nb + j * 32;
            float v[32];
#pragma unroll
            for (int i = 0; i < 32; i++)
                v[i] = __uint_as_float(r[i]) + load_elem(bias, n0 + i, flag);
            const size_t off = (size_t)m * N_TOTAL + n0;
            if (flag == 1) {
                float4* o = reinterpret_cast<float4*>((float*)C + off);
#pragma unroll
                for (int t = 0; t < 8; t++)
                    o[t] = make_float4(v[t*4], v[t*4+1], v[t*4+2], v[t*4+3]);
            } else if (flag == 2) {
                __nv_bfloat16 h[32];
#pragma unroll
                for (int i = 0; i < 32; i++) h[i] = __float2bfloat16(v[i]);
                uint4* o = reinterpret_cast<uint4*>((__nv_bfloat16*)C + off);
#pragma unroll
                for (int t = 0; t < 4; t++) o[t] = reinterpret_cast<uint4*>(h)[t];
            } else {
                __half h[32];
#pragma unroll
                for (int i = 0; i < 32; i++) h[i] = __float2half(v[i]);
                uint4* o = reinterpret_cast<uint4*>((__half*)C + off);
#pragma unroll
                for (int t = 0; t < 4; t++) o[t] = reinterpret_cast<uint4*>(h)[t];
            }
        }
    }

    __syncthreads();
    TCGEN05_FENCE_BEFORE();
    if (wid == 0) TCGEN05_DEALLOC(tmem, 512);
#endif  // HAS_TCGEN05
}

// ===========================================================================
// Launch
// ===========================================================================
typedef CUresult (*EncodeTiledFn)(
    CUtensorMap*, CUtensorMapDataType, cuuint32_t, void*,
    const cuuint64_t*, const cuuint64_t*, const cuuint32_t*, const cuuint32_t*,
    CUtensorMapInterleave, CUtensorMapSwizzle, CUtensorMapL2promotion,
    CUtensorMapFloatOOBfill);

static void make_map_2d(EncodeTiledFn fn, CUtensorMap* m, void* base) {
    cuuint64_t dims[2]    = {K_TOTAL, 4096};                 // dim0 = K (contiguous)
    cuuint64_t strides[1] = {(cuuint64_t)K_TOTAL * 2};       // bytes per row
    cuuint32_t box[2]     = {BKT, BM};                        // 64 halves (128B) x 256 rows
    cuuint32_t estr[2]    = {1, 1};
    fn(m, CU_TENSOR_MAP_DATA_TYPE_FLOAT16, 2, base, dims, strides, box, estr,
       CU_TENSOR_MAP_INTERLEAVE_NONE, CU_TENSOR_MAP_SWIZZLE_128B,
       CU_TENSOR_MAP_L2_PROMOTION_L2_128B, CU_TENSOR_MAP_FLOAT_OOB_FILL_NONE);
}

#define GEMM_SMEM_BYTES (2048 + NSTAGE * STAGE_BYTES)   // align slack + tiles

extern "C" void kernel_launch(void* const* d_in, const int* in_sizes, int n_in,
                              void* d_out, int out_size) {
    int ix = 0, iw = 1, is = 2, iz = 3, ib = 4;  // dict order default
    if (n_in >= 5 && in_sizes[1] == 4096) {      // alphabetical order
        iw = 0; ib = 1; is = 2; ix = 3; iz = 4;
    }
    const void* x     = d_in[ix];
    const int*  Wq    = (const int*)d_in[iw];
    const void* scale = d_in[is];
    const void* zero  = d_in[iz];
    const void* bias  = d_in[ib];

    detect_dtype_kernel<<<1, 256>>>(x);
    {
        size_t total8 = (size_t)M_TOTAL * K_TOTAL / 8;
        convert_x_kernel<<<(int)((total8 + 255) / 256), 256>>>(x);
    }
    {
        size_t total8 = (size_t)N_TOTAL * K_TOTAL / 8;
        dequant_kernel<<<(int)((total8 + 255) / 256), 256>>>(Wq, scale, zero);
    }

    // tcgen05 GEMM with TMA tensormaps (built host-side, passed by value)
    void* pX = nullptr;
    void* pW = nullptr;
    cudaGetSymbolAddress(&pX, g_X);
    cudaGetSymbolAddress(&pW, g_Wd);

    EncodeTiledFn encode = nullptr;
    cudaDriverEntryPointQueryResult qr;
    cudaGetDriverEntryPointByVersion("cuTensorMapEncodeTiled", (void**)&encode,
                                     12000, cudaEnableDefault, &qr);

    CUtensorMap tmA, tmB;
    make_map_2d(encode, &tmA, pX);
    make_map_2d(encode, &tmB, pW);

    cudaFuncSetAttribute(gemm_tc, cudaFuncAttributeMaxDynamicSharedMemorySize,
                         GEMM_SMEM_BYTES);
    dim3 grid(N_TOTAL / BN, M_TOTAL / BM);
    gemm_tc<<<grid, 128, GEMM_SMEM_BYTES>>>(tmA, tmB, bias, d_out);
}